// round 10
// baseline (speedup 1.0000x reference)
#include <cuda_runtime.h>

#define NP 262144          // 512*512 pixels
#define HDIM 96

typedef unsigned long long u64;

// ---- f32x2 packed-FMA helpers (sm_100+; FFMA2 in SASS) ----------------------
__device__ __forceinline__ u64 pk2(float lo, float hi) {
    u64 r; asm("mov.b64 %0, {%1, %2};" : "=l"(r) : "f"(lo), "f"(hi)); return r;
}
__device__ __forceinline__ u64 bc2(float v) { return pk2(v, v); }
__device__ __forceinline__ void fma2(u64& d, u64 a, u64 b) {
    asm("fma.rn.f32x2 %0, %1, %2, %0;" : "+l"(d) : "l"(a), "l"(b));
}
__device__ __forceinline__ void upk2(float& lo, float& hi, u64 v) {
    asm("mov.b64 {%0, %1}, %2;" : "=f"(lo), "=f"(hi) : "l"(v));
}
union F4U { float4 v; u64 u[2]; };

// Scratch (allowed: __device__ globals)
__device__ float g_mid[(size_t)HDIM * NP];   // attention output, pre-proj

// ---------------------------------------------------------------------------
// Proj SGEMM: C[o][p] = sum_i A[o][i] * g_mid[i][p] + bias[o]
// K = 96, BM = 96, BN = 128, 256 threads, 6x8 micro-tile, f32x2 MACs.
// ---------------------------------------------------------------------------
__global__ __launch_bounds__(256) void k_gemm_proj(const float* __restrict__ A,
                                                   const float* __restrict__ bias,
                                                   float* __restrict__ C) {
    __shared__ __align__(16) float As[48][96];
    __shared__ __align__(16) float Bs[48][128];

    const int t  = threadIdx.x;
    const int tx = t & 15;
    const int ty = t >> 4;
    const size_t p0 = (size_t)blockIdx.x * 128;
    const float* __restrict__ B = g_mid;

    u64 acc[6][4];
#pragma unroll
    for (int m = 0; m < 6; m++) {
        u64 bv = bc2(bias[ty * 6 + m]);
#pragma unroll
        for (int n = 0; n < 4; n++) acc[m][n] = bv;
    }

    for (int kt = 0; kt < 2; kt++) {
        for (int idx = t; idx < 48 * 96; idx += 256) {
            int o = idx / 48, k = idx % 48;
            As[k][o] = A[o * 96 + kt * 48 + k];
        }
        for (int idx = t; idx < 48 * 32; idx += 256) {
            int k = idx >> 5, c4 = idx & 31;
            *(float4*)&Bs[k][c4 * 4] =
                *(const float4*)(B + (size_t)(kt * 48 + k) * NP + p0 + c4 * 4);
        }
        __syncthreads();

#pragma unroll 4
        for (int k = 0; k < 48; k++) {
            u64 a2[6];
#pragma unroll
            for (int m = 0; m < 6; m++) a2[m] = bc2(As[k][ty * 6 + m]);
            F4U b0, b1;
            b0.v = *(float4*)&Bs[k][tx * 4];
            b1.v = *(float4*)&Bs[k][64 + tx * 4];
#pragma unroll
            for (int m = 0; m < 6; m++) {
                fma2(acc[m][0], a2[m], b0.u[0]);
                fma2(acc[m][1], a2[m], b0.u[1]);
                fma2(acc[m][2], a2[m], b1.u[0]);
                fma2(acc[m][3], a2[m], b1.u[1]);
            }
        }
        __syncthreads();
    }

#pragma unroll
    for (int m = 0; m < 6; m++) {
        float* cp = C + (size_t)(ty * 6 + m) * NP + p0;
        F4U o0, o1;
        o0.u[0] = acc[m][0]; o0.u[1] = acc[m][1];
        o1.u[0] = acc[m][2]; o1.u[1] = acc[m][3];
        *(float4*)(cp + tx * 4)      = o0.v;
        *(float4*)(cp + 64 + tx * 4) = o1.v;
    }
}

// ---------------------------------------------------------------------------
// Fused per-(head, window) kernel, 256 threads (see R3 for structure).
// Hot MAC loops converted to packed f32x2.
// ---------------------------------------------------------------------------
// smem offsets (floats)
#define OFF_XS   0        // [96][64]             (dead after GEMM)
#define OFF_W    6144     // [48][97]             (dead after GEMM)
#define OFF_ASP  0        // [64][64]   overlays XS
#define OFF_TMP  4096     // [16][64]   overlays XS
#define OFF_ACH  5120     // [16][17]   overlays XS tail
#define OFF_RAW  10800    // [48][64]
#define OFF_CV   13872    // [48][68]   (padded stride 68)
#define OFF_DWW  17136    // [48][9]
#define OFF_DWB  17568    // [48]
#define OFF_BT   17616    // [225]
#define SMEM_FLOATS 17856
#define SMEM_BYTES  (SMEM_FLOATS * 4)

__global__ __launch_bounds__(256) void window_attn_fused(
        const float* __restrict__ x,
        const float* __restrict__ qkv_w,
        const float* __restrict__ qkv_b,
        const float* __restrict__ dw_w,
        const float* __restrict__ dw_b,
        const float* __restrict__ temperature,
        const float* __restrict__ bias_table) {
    extern __shared__ __align__(16) float sm[];
    float* XS  = sm + OFF_XS;
    float* Wt  = sm + OFF_W;
    float* ASP = sm + OFF_ASP;
    float* TMP = sm + OFF_TMP;
    float* ACH = sm + OFF_ACH;
    float* RAW = sm + OFF_RAW;
    float* CV  = sm + OFF_CV;
    float* DWW = sm + OFF_DWW;
    float* DWB = sm + OFF_DWB;
    float* BT  = sm + OFF_BT;

    const int t   = threadIdx.x;
    const int h   = blockIdx.x;      // 0..5
    const int win = blockIdx.y;      // 0..4095
    const int wy  = win >> 6, wx = win & 63;
    const size_t base = (size_t)(wy * 8) * 512 + (size_t)wx * 8;

    // ---- phase 0: loads ----
    for (int i = t; i < 1536; i += 256) {
        int ch = i >> 4, r = i & 15;
        int dy = r >> 1, half = r & 1;
        *(float4*)&XS[ch * 64 + dy * 8 + half * 4] =
            *(const float4*)(x + (size_t)ch * NP + base + (size_t)dy * 512 + half * 4);
    }
    for (int i = t; i < 1152; i += 256) {
        int row = i / 24, c4 = i % 24;
        int gch = (row >> 4) * 96 + h * 16 + (row & 15);
        float4 wv = *(const float4*)(qkv_w + gch * 96 + c4 * 4);
        float* d = &Wt[row * 97 + c4 * 4];
        d[0] = wv.x; d[1] = wv.y; d[2] = wv.z; d[3] = wv.w;
    }
    for (int i = t; i < 432; i += 256) {
        int cl = i / 9, j = i % 9;
        int gch = (cl >> 4) * 96 + h * 16 + (cl & 15);
        DWW[cl * 9 + j] = dw_w[gch * 9 + j];
    }
    if (t < 48) {
        int gch = (t >> 4) * 96 + h * 16 + (t & 15);
        DWB[t] = dw_b[gch];
    }
    for (int i = t; i < 225; i += 256) BT[i] = bias_table[i * 6 + h];
    __syncthreads();

    // ---- phase 1: qkv GEMM -> RAW[48][64] (+bias), f32x2 ----
    {
        const int r0 = t >> 4;       // 0..15
        const int tx = t & 15;       // 4 cols each
        u64 a0r[2], a1r[2], a2r[2];
        {
            u64 b0 = bc2(qkv_b[0 * 96 + h * 16 + r0]);
            u64 b1 = bc2(qkv_b[1 * 96 + h * 16 + r0]);
            u64 b2 = bc2(qkv_b[2 * 96 + h * 16 + r0]);
            a0r[0] = b0; a0r[1] = b0;
            a1r[0] = b1; a1r[1] = b1;
            a2r[0] = b2; a2r[1] = b2;
        }
#pragma unroll 4
        for (int k = 0; k < 96; k++) {
            F4U bx; bx.v = *(float4*)&XS[k * 64 + tx * 4];
            u64 w0 = bc2(Wt[r0 * 97 + k]);
            u64 w1 = bc2(Wt[(r0 + 16) * 97 + k]);
            u64 w2 = bc2(Wt[(r0 + 32) * 97 + k]);
            fma2(a0r[0], w0, bx.u[0]); fma2(a0r[1], w0, bx.u[1]);
            fma2(a1r[0], w1, bx.u[0]); fma2(a1r[1], w1, bx.u[1]);
            fma2(a2r[0], w2, bx.u[0]); fma2(a2r[1], w2, bx.u[1]);
        }
        F4U o0, o1, o2;
        o0.u[0] = a0r[0]; o0.u[1] = a0r[1];
        o1.u[0] = a1r[0]; o1.u[1] = a1r[1];
        o2.u[0] = a2r[0]; o2.u[1] = a2r[1];
        *(float4*)&RAW[r0 * 64 + tx * 4]        = o0.v;
        *(float4*)&RAW[(r0 + 16) * 64 + tx * 4] = o1.v;
        *(float4*)&RAW[(r0 + 32) * 64 + tx * 4] = o2.v;
    }
    __syncthreads();

    // ---- phase 2: depthwise 3x3 (zero pad at window border) -> CV ----
    for (int i = t; i < 3072; i += 256) {
        int cl = i >> 6, pos = i & 63;
        int dy = pos >> 3, dx = pos & 7;
        float acc = DWB[cl];
#pragma unroll
        for (int ky = 0; ky < 3; ky++) {
            int yy = dy + ky - 1;
            if (yy < 0 || yy >= 8) continue;
#pragma unroll
            for (int kx = 0; kx < 3; kx++) {
                int xx = dx + kx - 1;
                if (xx < 0 || xx >= 8) continue;
                acc += DWW[cl * 9 + ky * 3 + kx] * RAW[cl * 64 + yy * 8 + xx];
            }
        }
        CV[cl * 68 + pos] = acc;
    }
    __syncthreads();

    // ---- phase 3: L2-normalize q rows (0-15) and k rows (16-31) over N=64 ----
    {
        int r  = t >> 3;             // 0..31
        int l8 = t & 7;              // 8 elems each
        float* rp = &CV[r * 68 + l8 * 8];
        float4 v0 = *(float4*)rp;
        float4 v1 = *(float4*)(rp + 4);
        float s = v0.x*v0.x + v0.y*v0.y + v0.z*v0.z + v0.w*v0.w
                + v1.x*v1.x + v1.y*v1.y + v1.z*v1.z + v1.w*v1.w;
        s += __shfl_xor_sync(0xffffffffu, s, 1);
        s += __shfl_xor_sync(0xffffffffu, s, 2);
        s += __shfl_xor_sync(0xffffffffu, s, 4);
        float nf = 1.0f / fmaxf(sqrtf(s), 1e-12f);
        v0.x *= nf; v0.y *= nf; v0.z *= nf; v0.w *= nf;
        v1.x *= nf; v1.y *= nf; v1.z *= nf; v1.w *= nf;
        *(float4*)rp       = v0;
        *(float4*)(rp + 4) = v1;
    }
    __syncthreads();

    const float tempv = temperature[h];

    // ---- phase 4: channel attention logits ACH[c][d] (stride 17), f32x2 ----
    {
        int c = t >> 4, d = t & 15;
        u64 s2 = 0ull;
#pragma unroll
        for (int n4 = 0; n4 < 16; n4++) {
            F4U q4, k4;
            q4.v = *(float4*)&CV[c * 68 + n4 * 4];
            k4.v = *(float4*)&CV[(16 + d) * 68 + n4 * 4];
            fma2(s2, q4.u[0], k4.u[0]);
            fma2(s2, q4.u[1], k4.u[1]);
        }
        float lo, hi; upk2(lo, hi, s2);
        ACH[c * 17 + d] = (lo + hi) * tempv;
    }

    // ---- phase 5: spatial attention logits + rel bias -> ASP[n][m], f32x2 ----
    {
        int m  = t & 63;
        int ng = t >> 6;             // n block of 16
        u64 kb2[16];
#pragma unroll
        for (int c = 0; c < 16; c++) kb2[c] = bc2(CV[(16 + c) * 68 + m]);
        u64 acc[8];
#pragma unroll
        for (int j = 0; j < 8; j++) acc[j] = 0ull;
#pragma unroll
        for (int c = 0; c < 16; c++) {
            u64 kv = kb2[c];
            F4U q0, q1, q2, q3;
            q0.v = *(float4*)&CV[c * 68 + ng * 16];
            q1.v = *(float4*)&CV[c * 68 + ng * 16 + 4];
            q2.v = *(float4*)&CV[c * 68 + ng * 16 + 8];
            q3.v = *(float4*)&CV[c * 68 + ng * 16 + 12];
            fma2(acc[0], q0.u[0], kv); fma2(acc[1], q0.u[1], kv);
            fma2(acc[2], q1.u[0], kv); fma2(acc[3], q1.u[1], kv);
            fma2(acc[4], q2.u[0], kv); fma2(acc[5], q2.u[1], kv);
            fma2(acc[6], q3.u[0], kv); fma2(acc[7], q3.u[1], kv);
        }
#pragma unroll
        for (int j = 0; j < 8; j++) {
            float lo, hi; upk2(lo, hi, acc[j]);
            int n0 = ng * 16 + j * 2;
            int rp0 = ((n0 >> 3) - (m >> 3) + 7) * 15 + ((n0 & 7) - (m & 7) + 7);
            int n1 = n0 + 1;
            int rp1 = ((n1 >> 3) - (m >> 3) + 7) * 15 + ((n1 & 7) - (m & 7) + 7);
            ASP[n0 * 64 + m] = lo + BT[rp0];
            ASP[n1 * 64 + m] = hi + BT[rp1];
        }
    }
    __syncthreads();

    // ---- phase 6: softmax over ASP rows (4 threads per row) ----
    {
        int r  = t >> 2;
        int l4 = t & 3;
        float* rp = &ASP[r * 64 + l4 * 16];
        float4 v[4];
#pragma unroll
        for (int g = 0; g < 4; g++) v[g] = *(float4*)(rp + g * 4);
        float mx = -1e30f;
#pragma unroll
        for (int g = 0; g < 4; g++)
            mx = fmaxf(mx, fmaxf(fmaxf(v[g].x, v[g].y), fmaxf(v[g].z, v[g].w)));
        mx = fmaxf(mx, __shfl_xor_sync(0xffffffffu, mx, 1));
        mx = fmaxf(mx, __shfl_xor_sync(0xffffffffu, mx, 2));
        float sum = 0.f;
#pragma unroll
        for (int g = 0; g < 4; g++) {
            v[g].x = __expf(v[g].x - mx); v[g].y = __expf(v[g].y - mx);
            v[g].z = __expf(v[g].z - mx); v[g].w = __expf(v[g].w - mx);
            sum += v[g].x + v[g].y + v[g].z + v[g].w;
        }
        sum += __shfl_xor_sync(0xffffffffu, sum, 1);
        sum += __shfl_xor_sync(0xffffffffu, sum, 2);
        float inv = 1.0f / sum;
#pragma unroll
        for (int g = 0; g < 4; g++) {
            v[g].x *= inv; v[g].y *= inv; v[g].z *= inv; v[g].w *= inv;
            *(float4*)(rp + g * 4) = v[g];
        }
    }
    __syncthreads();

    // ---- phase 7: TMP = softmax(ACH) @ v  (ach softmax in-register), f32x2 ----
    {
        int c  = t >> 4;
        int nb = (t & 15) * 4;
        float a[16];
#pragma unroll
        for (int d = 0; d < 16; d++) a[d] = ACH[c * 17 + d];
        float mx = -1e30f;
#pragma unroll
        for (int d = 0; d < 16; d++) mx = fmaxf(mx, a[d]);
        float sum = 0.f;
#pragma unroll
        for (int d = 0; d < 16; d++) { a[d] = __expf(a[d] - mx); sum += a[d]; }
        float inv = 1.0f / sum;
        u64 acc0 = 0ull, acc1 = 0ull;
#pragma unroll
        for (int d = 0; d < 16; d++) {
            u64 w = bc2(a[d] * inv);
            F4U v4; v4.v = *(float4*)&CV[(32 + d) * 68 + nb];
            fma2(acc0, w, v4.u[0]);
            fma2(acc1, w, v4.u[1]);
        }
        F4U o; o.u[0] = acc0; o.u[1] = acc1;
        *(float4*)&TMP[c * 64 + nb] = o.v;
    }
    __syncthreads();

    // ---- phase 8: out[c][m] = sum_n TMP[c][n] * ASP[n][m] -> g_mid, f32x2 ----
    {
        int c  = t >> 4;
        int mb = (t & 15) * 4;
        u64 acc0 = 0ull, acc1 = 0ull;
#pragma unroll 8
        for (int n = 0; n < 64; n++) {
            u64 a = bc2(TMP[c * 64 + n]);
            F4U p4; p4.v = *(float4*)&ASP[n * 64 + mb];
            fma2(acc0, a, p4.u[0]);
            fma2(acc1, a, p4.u[1]);
        }
        int dy = mb >> 3, dx = mb & 7;
        float* op = g_mid + (size_t)(h * 16 + c) * NP + base + (size_t)dy * 512 + dx;
        F4U o; o.u[0] = acc0; o.u[1] = acc1;
        *(float4*)op = o.v;
    }
}

// ---------------------------------------------------------------------------
extern "C" void kernel_launch(void* const* d_in, const int* in_sizes, int n_in,
                              void* d_out, int out_size) {
    const float* x      = (const float*)d_in[0];
    const float* qkv_w  = (const float*)d_in[1];
    const float* qkv_b  = (const float*)d_in[2];
    const float* dw_w   = (const float*)d_in[3];
    const float* dw_b   = (const float*)d_in[4];
    const float* proj_w = (const float*)d_in[5];
    const float* proj_b = (const float*)d_in[6];
    const float* temp   = (const float*)d_in[7];
    const float* btab   = (const float*)d_in[8];
    float* out = (float*)d_out;

    static bool attr_set = false;
    if (!attr_set) {
        cudaFuncSetAttribute(window_attn_fused,
                             cudaFuncAttributeMaxDynamicSharedMemorySize, SMEM_BYTES);
        attr_set = true;
    }

    dim3 g2(6, 4096);
    window_attn_fused<<<g2, 256, SMEM_BYTES>>>(x, qkv_w, qkv_b, dw_w, dw_b, temp, btab);

    dim3 g3(2048, 1);
    k_gemm_proj<<<g3, 256>>>(proj_w, proj_b, out);
}